// round 10
// baseline (speedup 1.0000x reference)
#include <cuda_runtime.h>
#include <cuda_bf16.h>
#include <cstdint>
#include <math.h>

#define B_    16
#define N_    4096
#define CIN   256
#define CH_   256
#define DW    512
#define IN_   128
#define NTILES_TOTAL 512     // 128-row tiles (fallback)
#define GRID_GEMM 128
#define UNITS 2              // 256 super-tiles of 256 rows / 128 CTAs

// tcgen05 asm only compiles under an 'a'-suffixed target pass.
#if defined(__CUDA_ARCH_FEAT_SM103_ALL) || defined(__CUDA_ARCH_FEAT_SM100_ALL) || defined(__CUDA_ARCH_FEAT_SM101_ALL)
#define USE_TCGEN05 1
#else
#define USE_TCGEN05 0
#endif

// -------------------- device scratch --------------------
__device__ float g_attw[B_ * DW];
// 16 pre-swizzled W chunk images of 32KB each (256 rows x 128B, SW128 baked in).
// chunk j = kb*4 + islo*2 + h.
// Row perm: w_conv row d (c=d&255, r=d>>8) -> h=c>>7, local row=(c&127)+r*128.
// D col (within N=256 MMA) = (c&127) + r*128; channel group = h.
__device__ __nv_bfloat16 g_w3[16 * 256 * 64];

// -------------------- PTX helpers --------------------
__device__ __forceinline__ uint32_t smem_u32(const void* p) {
    uint32_t a;
    asm("{ .reg .u64 t; cvta.to.shared.u64 t, %1; cvt.u32.u64 %0, t; }" : "=r"(a) : "l"(p));
    return a;
}
__device__ __forceinline__ uint32_t elect_one() {
    uint32_t pred;
    asm volatile("{\n\t.reg .pred p;\n\telect.sync _|p, 0xFFFFFFFF;\n\tselp.b32 %0, 1, 0, p;\n\t}" : "=r"(pred));
    return pred;
}
#define TCGEN05_ALLOC(sa, n) \
    asm volatile("tcgen05.alloc.cta_group::1.sync.aligned.shared::cta.b32 [%0], %1;" :: "r"((uint32_t)(sa)), "r"((uint32_t)(n)) : "memory")
#define TCGEN05_DEALLOC(t, n) \
    asm volatile("tcgen05.dealloc.cta_group::1.sync.aligned.b32 %0, %1;" :: "r"(t), "r"((uint32_t)(n)))
#define TCGEN05_RELINQ() \
    asm volatile("tcgen05.relinquish_alloc_permit.cta_group::1.sync.aligned;")
#define TCGEN05_COMMIT(mb) \
    asm volatile("tcgen05.commit.cta_group::1.mbarrier::arrive::one.shared::cluster.b64 [%0];" :: "r"((uint32_t)(mb)) : "memory")
#define TCGEN05_WAIT_LD() asm volatile("tcgen05.wait::ld.sync.aligned;" ::: "memory")
#define TCGEN05_FENCE_AFTER() asm volatile("tcgen05.fence::after_thread_sync;" ::: "memory")
#define MBARRIER_INIT(mb, cnt) \
    asm volatile("mbarrier.init.shared.b64 [%0], %1;" :: "r"((uint32_t)(mb)), "r"((uint32_t)(cnt)) : "memory")
#define MBARRIER_ARRIVE(mb) \
    asm volatile("mbarrier.arrive.shared.b64 _, [%0];" :: "r"((uint32_t)(mb)) : "memory")
#define MBARRIER_EXPECT_TX(mb, bytes) \
    asm volatile("mbarrier.arrive.expect_tx.shared.b64 _, [%0], %1;" :: "r"((uint32_t)(mb)), "r"((uint32_t)(bytes)) : "memory")
#define MBARRIER_WAIT_PARITY(mb, ph) do { \
    uint32_t _m = (uint32_t)(mb), _p = (uint32_t)(ph), _d; \
    asm volatile("{\n\t.reg .pred p;\n\tmbarrier.try_wait.parity.acquire.cta.shared::cta.b64 p, [%1], %2;\n\tselp.b32 %0, 1, 0, p;\n\t}" \
        : "=r"(_d) : "r"(_m), "r"(_p) : "memory"); \
    if (!_d) { \
        asm volatile("{\n\t.reg .pred P1;\n\tWL_%=:\n\tmbarrier.try_wait.parity.acquire.cta.shared::cta.b64 P1, [%0], %1, 0x989680;\n\t@P1 bra.uni WD_%=;\n\tbra.uni WL_%=;\n\tWD_%=:\n\t}" \
            :: "r"(_m), "r"(_p) : "memory"); \
    } \
} while (0)
#define BULK_G2S(dst, src, bytes, mb) \
    asm volatile("cp.async.bulk.shared::cta.global.mbarrier::complete_tx::bytes [%0], [%1], %2, [%3];" \
        :: "r"((uint32_t)(dst)), "l"(src), "r"((uint32_t)(bytes)), "r"((uint32_t)(mb)) : "memory")
#define TCGEN05_LD_X32(r, ta) \
    asm volatile("tcgen05.ld.sync.aligned.32x32b.x32.b32 " \
        "{%0,%1,%2,%3,%4,%5,%6,%7,%8,%9,%10,%11,%12,%13,%14,%15," \
        "%16,%17,%18,%19,%20,%21,%22,%23,%24,%25,%26,%27,%28,%29,%30,%31}, [%32];" \
        : "=r"((r)[0]),"=r"((r)[1]),"=r"((r)[2]),"=r"((r)[3]),"=r"((r)[4]),"=r"((r)[5]),"=r"((r)[6]),"=r"((r)[7]), \
          "=r"((r)[8]),"=r"((r)[9]),"=r"((r)[10]),"=r"((r)[11]),"=r"((r)[12]),"=r"((r)[13]),"=r"((r)[14]),"=r"((r)[15]), \
          "=r"((r)[16]),"=r"((r)[17]),"=r"((r)[18]),"=r"((r)[19]),"=r"((r)[20]),"=r"((r)[21]),"=r"((r)[22]),"=r"((r)[23]), \
          "=r"((r)[24]),"=r"((r)[25]),"=r"((r)[26]),"=r"((r)[27]),"=r"((r)[28]),"=r"((r)[29]),"=r"((r)[30]),"=r"((r)[31]) \
        : "r"(ta))

static constexpr uint64_t SMEM_DESC_BASE_SW128 =
    (uint64_t(2) << 61) | (uint64_t(1) << 46) | (uint64_t(64) << 32) | (uint64_t(1) << 16);
#define MAKE_SMEM_DESC(a) (SMEM_DESC_BASE_SW128 | ((uint64_t)((a) >> 4) & 0x3FFF))

#if USE_TCGEN05
// SS-mode cg1 bf16 MMA: D[128,256] += A[128,16] * B[256,16]^T
__device__ __forceinline__ void mma_f16_ss(uint32_t d, uint64_t ad, uint64_t bd, uint32_t idesc, bool acc) {
    uint32_t en = acc ? 1u : 0u;
    asm volatile(
        "{\n\t.reg .pred p;\n\tsetp.ne.u32 p, %5, 0;\n\t"
        "tcgen05.mma.cta_group::1.kind::f16 [%0], %1, %2, %3, {%4, %4, %4, %4}, p;\n\t}"
        :: "r"(d), "l"(ad), "l"(bd), "r"(idesc), "r"(0u), "r"(en) : "memory");
}
#endif
// idesc: F32 accum, BF16 x BF16, M=128, N=256
static constexpr uint32_t IDESC =
    (1u << 4) | (1u << 7) | (1u << 10) | ((256u / 8u) << 17) | ((128u / 16u) << 24);

// fp32 -> bf16 hi/lo split, packed pairs
__device__ __forceinline__ void split4(const float4 v, uint32_t& h01, uint32_t& h23,
                                       uint32_t& l01, uint32_t& l23) {
    __nv_bfloat162 h0 = __floats2bfloat162_rn(v.x, v.y);
    __nv_bfloat162 h1 = __floats2bfloat162_rn(v.z, v.w);
    __nv_bfloat162 l0 = __floats2bfloat162_rn(v.x - __bfloat162float(h0.x),
                                              v.y - __bfloat162float(h0.y));
    __nv_bfloat162 l1 = __floats2bfloat162_rn(v.z - __bfloat162float(h1.x),
                                              v.w - __bfloat162float(h1.y));
    h01 = *(uint32_t*)&h0; h23 = *(uint32_t*)&h1;
    l01 = *(uint32_t*)&l0; l23 = *(uint32_t*)&l1;
}

// ---------------------------------------------------------------------------
// Setup (single launch): blocks 0..15 = full attention chain (conv inline);
// blocks 16..143 = prep_w. Independent -> one kernel.
// Only rows n=0 / n=1024 per batch survive the rSoftMax slice; b_fc2 cancels.
// ---------------------------------------------------------------------------
__global__ __launch_bounds__(256) void setup_kernel(
    const float* __restrict__ x,
    const float* __restrict__ w_conv,
    const float* __restrict__ b_conv,
    const float* __restrict__ w_fc1,
    const float* __restrict__ b_fc1,
    const float* __restrict__ w_fc2)
{
    const int tid = threadIdx.x;

    if (blockIdx.x >= 16) {
        // ---- prep_w: 128 blocks x 256 threads x 4 floats ----
        const int gi = ((blockIdx.x - 16) * 256 + tid) * 4;
        float4 v = *(const float4*)(w_conv + gi);
        const int d = gi >> 8, k = gi & 255;
        uint32_t h01, h23, l01, l23;
        split4(v, h01, h23, l01, l23);
        const int c = d & 255, r = d >> 8;
        const int nh = c >> 7;
        const int lrow = (c & 127) + (r << 7);
        const int kb = k >> 6, kc = k & 63;
        const uint32_t off = (uint32_t)lrow * 128 + (((uint32_t)kc * 2) ^ ((uint32_t)(lrow & 7) << 4));
        char* basehi = (char*)g_w3 + (size_t)(kb * 4 + nh) * 32768 + off;
        char* baselo = (char*)g_w3 + (size_t)(kb * 4 + 2 + nh) * 32768 + off;
        *(uint2*)basehi = make_uint2(h01, h23);
        *(uint2*)baselo = make_uint2(l01, l23);
        return;
    }

    // ---- attention (conv inline) ----
    const int b = blockIdx.x;
    __shared__ float xs0[CIN], xs1[CIN];
    __shared__ float h0[DW], h1[DW];
    __shared__ float gap0[CH_], gap1[CH_];
    __shared__ float g0[IN_], g1[IN_], gd[IN_];

    xs0[tid] = x[(b * N_ + 0)    * CIN + tid];
    xs1[tid] = x[(b * N_ + 1024) * CIN + tid];
    __syncthreads();

    #pragma unroll
    for (int dd = 0; dd < 2; dd++) {
        const int d = tid + dd * 256;
        const float4* w = (const float4*)(w_conv + d * CIN);
        float s0 = 0.f, s1 = 0.f;
        #pragma unroll 8
        for (int k4 = 0; k4 < CIN / 4; k4++) {
            float4 wv = w[k4];
            float4 x0 = ((const float4*)xs0)[k4];
            float4 x1 = ((const float4*)xs1)[k4];
            s0 += wv.x * x0.x + wv.y * x0.y + wv.z * x0.z + wv.w * x0.w;
            s1 += wv.x * x1.x + wv.y * x1.y + wv.z * x1.z + wv.w * x1.w;
        }
        const float bb = b_conv[d];
        h0[d] = fmaxf(s0 + bb, 0.f);
        h1[d] = fmaxf(s1 + bb, 0.f);
    }
    __syncthreads();

    gap0[tid] = h0[tid] + h0[tid + CH_];
    gap1[tid] = h1[tid] + h1[tid + CH_];
    __syncthreads();

    {
        const int i = tid & 127;
        const float* gp = (tid < 128) ? gap0 : gap1;
        const float4* w = (const float4*)(w_fc1 + i * CH_);
        float s = 0.f;
        #pragma unroll 8
        for (int k4 = 0; k4 < CH_ / 4; k4++) {
            float4 wv = w[k4];
            float4 gv = ((const float4*)gp)[k4];
            s += wv.x * gv.x + wv.y * gv.y + wv.z * gv.z + wv.w * gv.w;
        }
        s = fmaxf(s + b_fc1[i], 0.f);
        if (tid < 128) g0[i] = s; else g1[i] = s;
    }
    __syncthreads();
    if (tid < IN_) gd[tid] = g0[tid] - g1[tid];
    __syncthreads();

    #pragma unroll
    for (int dd = 0; dd < 2; dd++) {
        const int d = tid + dd * 256;
        const float4* w = (const float4*)(w_fc2 + d * IN_);
        float s = 0.f;
        #pragma unroll 8
        for (int k4 = 0; k4 < IN_ / 4; k4++) {
            float4 wv = w[k4];
            float4 gv = ((const float4*)gd)[k4];
            s += wv.x * gv.x + wv.y * gv.y + wv.z * gv.z + wv.w * gv.w;
        }
        g_attw[b * DW + d] = 1.f / (1.f + expf(-s));
    }
}

// ---------------------------------------------------------------------------
// GEMM: persistent cg1 tcgen05, M=256 SUPER-TILES. Two 128-row sub-tiles per
// CTA share every W chunk (W demand 21 B/cyc/SM = 50% of LTS cap). TMEM holds
// ONE half at a time (sub0 -> cols 0..255, sub1 -> 256..511); halves are
// strictly serialized on TMEM: MMA of half gh waits EPIF of half gh-1
// (fix for the round-9 race where h=1 overwrote h=0 mid-epilogue).
// Warp0 MMA, warp1 W producer, warps2-9 epilogue, warps10-15 A loaders.
// ---------------------------------------------------------------------------
#define A_OFF   1024
#define W_OFF   (1024 + 2 * 65536)
#define SMEM_TOTAL (1024 + 2 * 65536 + 3 * 32768)

__global__ __launch_bounds__(512, 1)
void gemm_kernel(const float* __restrict__ x,
                 const float* __restrict__ w_conv,
                 const float* __restrict__ b_conv,
                 float* __restrict__ out)
{
    extern __shared__ __align__(1024) char smem[];
    const int tid = threadIdx.x;

#if USE_TCGEN05
    const uint32_t sb = smem_u32(smem);
    const int wid = tid >> 5, lid = tid & 31;
    const int bid = blockIdx.x;
    const int NGH = UNITS * 2;   // global halves per CTA

    #define WF(s)   (sb + 8   + (s) * 8)
    #define WE(s)   (sb + 32  + (s) * 8)
    #define AF(q)   (sb + 56  + (q) * 8)
    #define AR(q)   (sb + 72  + (q) * 8)
    const uint32_t MDN  = sb + 88;
    const uint32_t EPIF = sb + 96;

    if (wid == 0) TCGEN05_ALLOC(sb, 512);
    if (tid == 0) {
        #pragma unroll
        for (int s = 0; s < 3; s++) { MBARRIER_INIT(WF(s), 1); MBARRIER_INIT(WE(s), 1); }
        MBARRIER_INIT(AF(0), 192); MBARRIER_INIT(AF(1), 192);
        MBARRIER_INIT(AR(0), 1);   MBARRIER_INIT(AR(1), 1);
        MBARRIER_INIT(MDN, 1);     MBARRIER_INIT(EPIF, 256);
    }
    __syncthreads();
    uint32_t tmem;
    asm volatile("ld.shared.b32 %0, [%1];" : "=r"(tmem) : "r"(sb));

    if (wid == 0) {
        // ================= MMA warp =================
        if (elect_one()) {
            int wst = 0;
            int wfph[3] = {0, 0, 0};
            int afph[2] = {0, 0};
            for (int gh = 0; gh < NGH; gh++) {
                // TMEM is fully used by one half: wait epilogue of previous half.
                if (gh > 0) MBARRIER_WAIT_PARITY(EPIF, (gh - 1) & 1);
                #pragma unroll 1
                for (int kb = 0; kb < 4; kb++) {
                    const int q = (gh * 4 + kb) & 1;
                    MBARRIER_WAIT_PARITY(AF(q), afph[q]); afph[q] ^= 1;
                    const uint32_t abase = sb + A_OFF + q * 65536;
                    // --- whi chunk: (ahi + alo) * whi, both sub-tiles ---
                    MBARRIER_WAIT_PARITY(WF(wst), wfph[wst]); wfph[wst] ^= 1;
                    {
                        const uint64_t wd = MAKE_SMEM_DESC(sb + W_OFF + wst * 32768);
                        #pragma unroll
                        for (int sub = 0; sub < 2; sub++) {
                            const uint32_t dst = tmem + sub * 256;
                            const uint64_t ah = MAKE_SMEM_DESC(abase + sub * 32768);
                            const uint64_t al = MAKE_SMEM_DESC(abase + sub * 32768 + 16384);
                            #pragma unroll
                            for (int k = 0; k < 4; k++)
                                mma_f16_ss(dst, ah + k * 2, wd + k * 2, IDESC, !(kb == 0 && k == 0));
                            #pragma unroll
                            for (int k = 0; k < 4; k++)
                                mma_f16_ss(dst, al + k * 2, wd + k * 2, IDESC, true);
                        }
                        TCGEN05_COMMIT(WE(wst));
                    }
                    wst = (wst == 2) ? 0 : wst + 1;
                    // --- wlo chunk: ahi * wlo, both sub-tiles ---
                    MBARRIER_WAIT_PARITY(WF(wst), wfph[wst]); wfph[wst] ^= 1;
                    {
                        const uint64_t wd = MAKE_SMEM_DESC(sb + W_OFF + wst * 32768);
                        #pragma unroll
                        for (int sub = 0; sub < 2; sub++) {
                            const uint32_t dst = tmem + sub * 256;
                            const uint64_t ah = MAKE_SMEM_DESC(abase + sub * 32768);
                            #pragma unroll
                            for (int k = 0; k < 4; k++)
                                mma_f16_ss(dst, ah + k * 2, wd + k * 2, IDESC, true);
                        }
                        TCGEN05_COMMIT(WE(wst));
                    }
                    wst = (wst == 2) ? 0 : wst + 1;
                    TCGEN05_COMMIT(AR(q));   // A stage q reusable
                }
                TCGEN05_COMMIT(MDN);         // half gh accumulators final
            }
        }
    } else if (wid == 1) {
        // ================= W producer: continuous 3-stage ring ==============
        if (elect_one()) {
            const char* wsrc = (const char*)g_w3;
            int wst = 0, wc = 0;
            int weph[3] = {0, 0, 0};
            for (int gh = 0; gh < NGH; gh++) {
                const int h = gh & 1;
                #pragma unroll 1
                for (int kb = 0; kb < 4; kb++)
                    #pragma unroll
                    for (int isl = 0; isl < 2; isl++) {
                        if (wc >= 3) { MBARRIER_WAIT_PARITY(WE(wst), weph[wst]); weph[wst] ^= 1; }
                        MBARRIER_EXPECT_TX(WF(wst), 32768);
                        BULK_G2S(sb + W_OFF + wst * 32768,
                                 wsrc + (size_t)(kb * 4 + isl * 2 + h) * 32768,
                                 32768, WF(wst));
                        wst = (wst == 2) ? 0 : wst + 1;
                        wc++;
                    }
            }
        }
    } else if (wid <= 9) {
        // ================= Epilogue (8 warps): warps 2-5 sub0, 6-9 sub1 =====
        const int sub = (wid - 2) >> 2;
        const int m   = (wid & 3) * 32 + lid;       // own TMEM subpartition rows
        for (int gh = 0; gh < NGH; gh++) {
            const int u = gh >> 1, h = gh & 1;
            const int m0 = (bid + GRID_GEMM * u) * 256;
            const int bb = m0 >> 12;
            const int n  = (m0 & (N_ - 1)) + sub * 128 + m;
            float* __restrict__ orow = out + ((size_t)n * B_ + bb) * CH_;
            const float* __restrict__ aw = g_attw + bb * DW;
            MBARRIER_WAIT_PARITY(MDN, gh & 1);
            TCGEN05_FENCE_AFTER();
            #pragma unroll 1
            for (int cc = 0; cc < 4; cc++) {
                uint32_t hr0[32], hr1[32];
                TCGEN05_LD_X32(hr0, tmem + sub * 256 + cc * 32);         // radix 0
                TCGEN05_LD_X32(hr1, tmem + sub * 256 + 128 + cc * 32);   // radix 1
                TCGEN05_WAIT_LD();
                #pragma unroll
                for (int qq = 0; qq < 8; qq++) {
                    const int ch = h * 128 + cc * 32 + qq * 4;
                    float4 b0 = *(const float4*)&b_conv[ch];
                    float4 b1 = *(const float4*)&b_conv[256 + ch];
                    float4 a0 = *(const float4*)&aw[ch];
                    float4 a1 = *(const float4*)&aw[256 + ch];
                    float4 o;
                    o.x = a0.x * fmaxf(__uint_as_float(hr0[qq*4+0]) + b0.x, 0.f)
                        + a1.x * fmaxf(__uint_as_float(hr1[qq*4+0]) + b1.x, 0.f);
                    o.y = a0.y * fmaxf(__uint_as_float(hr0[qq*4+1]) + b0.y, 0.f)
                        + a1.y * fmaxf(__uint_as_float(hr1[qq*4+1]) + b1.y, 0.f);
                    o.z = a0.z * fmaxf(__uint_as_float(hr0[qq*4+2]) + b0.z, 0.f)
                        + a1.z * fmaxf(__uint_as_float(hr1[qq*4+2]) + b1.z, 0.f);
                    o.w = a0.w * fmaxf(__uint_as_float(hr0[qq*4+3]) + b0.w, 0.f)
                        + a1.w * fmaxf(__uint_as_float(hr1[qq*4+3]) + b1.w, 0.f);
                    *(float4*)(orow + ch) = o;
                }
            }
            MBARRIER_ARRIVE(EPIF);   // TMEM free for next half
        }
    } else {
        // ================= A loaders (6 warps, 192 threads) =================
        const int lt = tid - 320;
        int arph[2] = {0, 0};
        int c = 0;
        for (int gh = 0; gh < NGH; gh++) {
            const int u = gh >> 1;
            const int m0 = (bid + GRID_GEMM * u) * 256;
            #pragma unroll 1
            for (int kb = 0; kb < 4; kb++) {
                const int q = c & 1;
                if (c >= 2) { MBARRIER_WAIT_PARITY(AR(q), arph[q]); arph[q] ^= 1; }
                const uint32_t abase = sb + A_OFF + q * 65536;
                for (int f = lt; f < 4096; f += 192) {
                    const int sub = f >> 11;
                    const int r   = (f >> 4) & 127;
                    const int qq  = f & 15;
                    const float4 v = *(const float4*)&x[(size_t)(m0 + sub * 128 + r) * 256 + kb * 64 + qq * 4];
                    uint32_t h01, h23, l01, l23;
                    split4(v, h01, h23, l01, l23);
                    const uint32_t off = (uint32_t)r * 128 + (((uint32_t)qq * 8) ^ ((uint32_t)(r & 7) << 4));
                    const uint32_t d0 = abase + sub * 32768 + off;
                    asm volatile("st.shared.v2.b32 [%0], {%1,%2};" :: "r"(d0), "r"(h01), "r"(h23) : "memory");
                    asm volatile("st.shared.v2.b32 [%0], {%1,%2};" :: "r"(d0 + 16384), "r"(l01), "r"(l23) : "memory");
                }
                asm volatile("fence.proxy.async.shared::cta;" ::: "memory");
                MBARRIER_ARRIVE(AF(q));
                c++;
            }
        }
    }

    __syncthreads();
    if (wid == 0) { TCGEN05_DEALLOC(tmem, 512); TCGEN05_RELINQ(); }

#else  // ------------------- fp32 FFMA fallback (plain sm_103) --------------
    float (*As)[64]  = (float(*)[64])smem;
    float (*Bs)[516] = (float(*)[516])(smem + 16 * 64 * 4);

    const int trow = tid >> 6;
    const int tcol = tid & 63;
    const int aM = tid >> 2, aK = (tid & 3) << 2;
    const int bD = tid >> 2, bK = (tid & 3) << 2;

    for (int tile = blockIdx.x; tile < NTILES_TOTAL; tile += gridDim.x) {
        const int m0 = tile * 128;
        const int bb = m0 >> 12;
        const int n0 = m0 & (N_ - 1);
        for (int sub = 0; sub < 2; sub++) {
            const int ms = m0 + sub * 64;
            float acc[8][8];
            #pragma unroll
            for (int i = 0; i < 8; i++)
                #pragma unroll
                for (int jj = 0; jj < 8; jj++) acc[i][jj] = 0.f;

            float4 aReg = make_float4(0.f, 0.f, 0.f, 0.f);
            float4 bReg[4];
            if (tid < 256)
                aReg = *(const float4*)&x[(size_t)(ms + aM) * CIN + aK];
            #pragma unroll
            for (int p = 0; p < 4; p++)
                bReg[p] = *(const float4*)&w_conv[(size_t)(bD + p * 128) * CIN + bK];

            for (int ks = 0; ks < CIN; ks += 16) {
                __syncthreads();
                if (tid < 256) {
                    As[aK + 0][aM] = aReg.x; As[aK + 1][aM] = aReg.y;
                    As[aK + 2][aM] = aReg.z; As[aK + 3][aM] = aReg.w;
                }
                #pragma unroll
                for (int p = 0; p < 4; p++) {
                    const int d = bD + p * 128;
                    Bs[bK + 0][d] = bReg[p].x; Bs[bK + 1][d] = bReg[p].y;
                    Bs[bK + 2][d] = bReg[p].z; Bs[bK + 3][d] = bReg[p].w;
                }
                __syncthreads();
                if (ks + 16 < CIN) {
                    const int kn = ks + 16;
                    if (tid < 256)
                        aReg = *(const float4*)&x[(size_t)(ms + aM) * CIN + kn + aK];
                    #pragma unroll
                    for (int p = 0; p < 4; p++)
                        bReg[p] = *(const float4*)&w_conv[(size_t)(bD + p * 128) * CIN + kn + bK];
                }
                #pragma unroll
                for (int k = 0; k < 16; k++) {
                    float a[8], bf[8];
                    *(float4*)&a[0]  = *(const float4*)&As[k][trow * 8];
                    *(float4*)&a[4]  = *(const float4*)&As[k][trow * 8 + 4];
                    *(float4*)&bf[0] = *(const float4*)&Bs[k][tcol * 4];
                    *(float4*)&bf[4] = *(const float4*)&Bs[k][tcol * 4 + 256];
                    #pragma unroll
                    for (int i = 0; i < 8; i++)
                        #pragma unroll
                        for (int jj = 0; jj < 8; jj++)
                            acc[i][jj] += a[i] * bf[jj];
                }
            }
            __syncthreads();

            const int cbase = tcol * 4;
            float a0[4], a1[4], bias0[4], bias1[4];
            #pragma unroll
            for (int jj = 0; jj < 4; jj++) {
                a0[jj]    = g_attw[bb * DW + cbase + jj];
                a1[jj]    = g_attw[bb * DW + 256 + cbase + jj];
                bias0[jj] = b_conv[cbase + jj];
                bias1[jj] = b_conv[256 + cbase + jj];
            }
            #pragma unroll
            for (int i = 0; i < 8; i++) {
                const int n = n0 + sub * 64 + trow * 8 + i;
                float4 o;
                o.x = a0[0] * fmaxf(acc[i][0] + bias0[0], 0.f) + a1[0] * fmaxf(acc[i][4] + bias1[0], 0.f);
                o.y = a0[1] * fmaxf(acc[i][1] + bias0[1], 0.f) + a1[1] * fmaxf(acc[i][5] + bias1[1], 0.f);
                o.z = a0[2] * fmaxf(acc[i][2] + bias0[2], 0.f) + a1[2] * fmaxf(acc[i][6] + bias1[2], 0.f);
                o.w = a0[3] * fmaxf(acc[i][3] + bias0[3], 0.f) + a1[3] * fmaxf(acc[i][7] + bias1[3], 0.f);
                *(float4*)&out[((size_t)n * B_ + bb) * CH_ + cbase] = o;
            }
        }
    }
#endif
}

extern "C" void kernel_launch(void* const* d_in, const int* in_sizes, int n_in,
                              void* d_out, int out_size) {
    const float* x      = (const float*)d_in[0];
    const float* w_conv = (const float*)d_in[1];
    const float* b_conv = (const float*)d_in[2];
    const float* w_fc1  = (const float*)d_in[3];
    const float* b_fc1  = (const float*)d_in[4];
    const float* w_fc2  = (const float*)d_in[5];
    // d_in[6] = b_fc2: cancels in the softmax-pair difference, unused.
    float* out = (float*)d_out;

    cudaFuncSetAttribute(gemm_kernel, cudaFuncAttributeMaxDynamicSharedMemorySize, SMEM_TOTAL);

    setup_kernel<<<144, 256>>>(x, w_conv, b_conv, w_fc1, b_fc1, w_fc2);
    gemm_kernel<<<GRID_GEMM, 512, SMEM_TOTAL>>>(x, w_conv, b_conv, out);
}